// round 7
// baseline (speedup 1.0000x reference)
#include <cuda_runtime.h>
#include <cuda_fp16.h>

#define NB 64
#define NC 64
#define NH 32
#define NW 32
#define NOC 128
#define NL 1024
#define PH 34

#define SAKH 72                        // A smem row stride in halves (conflict-free)
#define A_TAP_B (64 * SAKH * 2)        // 9216 B per tap stage
#define NASTG 4

// Scratch: x as fp16, [pixel=(y*34+x)][b][c], border zero.
__device__ __half g_xh[PH * PH * NB * NC];
__device__ unsigned int g_ctr;

// ---------------------------------------------------------------------------
__device__ __forceinline__ void cp16(unsigned int s, const void* g) {
    asm volatile("cp.async.cg.shared.global [%0], [%1], 16;" :: "r"(s), "l"(g));
}
__device__ __forceinline__ unsigned int pack_h2(float a, float b) {
    __half2 h = __floats2half2_rn(a, b);
    return *reinterpret_cast<unsigned int*>(&h);
}

// ---------------------------------------------------------------------------
// Kernel 0: zero border pixels of g_xh + reset work counter. grid 1156 x 128.
// ---------------------------------------------------------------------------
__global__ void __launch_bounds__(128) init_kernel() {
    if (blockIdx.x == 0 && threadIdx.x == 0) g_ctr = 0u;
    int p = blockIdx.x;
    int y = p / PH, xx = p % PH;
    if (y == 0 || y == PH - 1 || xx == 0 || xx == PH - 1) {
        uint4* dst = (uint4*)(g_xh + (size_t)p * (NB * NC));
        #pragma unroll
        for (int i = 0; i < 4; ++i)
            dst[threadIdx.x + i * 128] = make_uint4(0, 0, 0, 0);
    }
}

// ---------------------------------------------------------------------------
// Kernel 1: x[b][c][h][w] f32 -> g_xh[(h+1)*34+(w+1)][b][c] fp16.
// ---------------------------------------------------------------------------
__global__ void __launch_bounds__(256) transpose_half_kernel(const float* __restrict__ x) {
    __shared__ __half s[8][64][33];
    int h = blockIdx.x;
    int b0 = blockIdx.y * 8;
    int tid = threadIdx.x;
    for (int idx = tid; idx < 8 * 64 * 32; idx += 256) {
        int b = idx >> 11, c = (idx >> 5) & 63, w = idx & 31;
        float v = x[(((size_t)(b0 + b) * NC + c) * NH + h) * NW + w];
        s[b][c][w] = __float2half_rn(v);
    }
    __syncthreads();
    for (int idx = tid; idx < 32 * 8 * 64; idx += 256) {
        int w = idx >> 9, b = (idx >> 6) & 7, c = idx & 63;
        g_xh[((size_t)((h + 1) * PH + (w + 1)) * NB + (b0 + b)) * NC + c] = s[b][c][w];
    }
}

// ---------------------------------------------------------------------------
// Kernel 2: persistent per-location GEMM.
// C[64b x 128o] = A[64b x 576d] * W[576d x l x 128o].
// 8 warps, each owns 16 OC columns; W streamed global->registers (no smem B).
// A: fp16 x-patch taps in 4-stage rolling cp.async smem buffer.
// ---------------------------------------------------------------------------
__global__ void __launch_bounds__(256, 2) lc_kernel(
    const float* __restrict__ w, const float* __restrict__ bias,
    float* __restrict__ out)
{
    __shared__ __align__(16) __half sA[NASTG * 64 * SAKH];
    __shared__ int s_l;
    int tid = threadIdx.x, lane = tid & 31, wid = tid >> 5;
    int obase = wid * 16;                 // this warp's OC slice
    unsigned int sA_u = (unsigned int)__cvta_generic_to_shared(sA);

    const size_t PLANE = (size_t)NL * NOC;       // 131072 floats per d-row

    for (;;) {
        __syncthreads();                  // all reads of sA / s_l from prev loc done
        if (tid == 0) s_l = (int)atomicAdd(&g_ctr, 1u);
        __syncthreads();
        int l = s_l;
        if (l >= NL) break;
        int oh = l >> 5, ow = l & 31;

        // bias for this thread's output columns
        float bz[2][2];
        #pragma unroll
        for (int nt = 0; nt < 2; ++nt) {
            int c0 = obase + nt * 8 + 2 * (lane & 3);
            bz[nt][0] = __ldg(bias + (size_t)c0 * NL + l);
            bz[nt][1] = __ldg(bias + (size_t)(c0 + 1) * NL + l);
        }

        auto issueA = [&](int tap) {
            int pix = (oh + tap / 3) * PH + ow + tap % 3;
            const char* xs = (const char*)(g_xh + (size_t)pix * (NB * NC));
            unsigned int dst = sA_u + (unsigned)((tap & 3) * A_TAP_B);
            #pragma unroll
            for (int f = 0; f < 2; ++f) {
                int idx = tid + f * 256;
                int r = idx >> 3, j = idx & 7;
                cp16(dst + (unsigned)(r * (SAKH * 2) + j * 16), xs + r * 128 + j * 16);
            }
            asm volatile("cp.async.commit_group;");
        };

        issueA(0); issueA(1); issueA(2);

        float acc[4][2][4];
        #pragma unroll
        for (int mt = 0; mt < 4; ++mt)
            #pragma unroll
            for (int nt = 0; nt < 2; ++nt)
                #pragma unroll
                for (int q = 0; q < 4; ++q) acc[mt][nt][q] = 0.f;

        // B prefetch registers: one K=32 chunk (16 f32) ahead.
        int ct = (lane & 3) * 2;                      // k-pair base within 16
        int oc0 = obase + (lane >> 2);                // nt=0 column
        const size_t base_l = (size_t)l * NOC;

        float bpf[16];
        auto loadB = [&](int q) {                     // chunk q: tap=q>>1, half=q&1
            int tap = q >> 1;
            int ch32 = (q & 1) << 5;
            #pragma unroll
            for (int kk = 0; kk < 2; ++kk) {
                int cb = ch32 + kk * 16 + ct;
                #pragma unroll
                for (int nt = 0; nt < 2; ++nt) {
                    const float* p = w + (size_t)(cb * 9 + tap) * PLANE
                                       + base_l + (oc0 + nt * 8);
                    int j = kk * 8 + nt * 4;
                    bpf[j + 0] = __ldg(p);
                    bpf[j + 1] = __ldg(p + 9 * PLANE);
                    bpf[j + 2] = __ldg(p + 72 * PLANE);
                    bpf[j + 3] = __ldg(p + 81 * PLANE);
                }
            }
        };
        loadB(0);

        #pragma unroll 1
        for (int qc = 0; qc < 18; ++qc) {
            int tap = qc >> 1;
            if ((qc & 1) == 0) {
                // tap boundary: A[tap] must be resident
                if (tap <= 6)      asm volatile("cp.async.wait_group 2;" ::: "memory");
                else if (tap == 7) asm volatile("cp.async.wait_group 1;" ::: "memory");
                else               asm volatile("cp.async.wait_group 0;" ::: "memory");
                __syncthreads();
                if (tap <= 5) issueA(tap + 3);
            }

            // convert current chunk's B to half2
            unsigned int bh[2][2][2];
            #pragma unroll
            for (int kk = 0; kk < 2; ++kk)
                #pragma unroll
                for (int nt = 0; nt < 2; ++nt) {
                    int j = kk * 8 + nt * 4;
                    bh[kk][nt][0] = pack_h2(bpf[j + 0], bpf[j + 1]);
                    bh[kk][nt][1] = pack_h2(bpf[j + 2], bpf[j + 3]);
                }
            // prefetch next chunk's B
            if (qc + 1 < 18) loadB(qc + 1);

            unsigned int aS = sA_u + (unsigned)((tap & 3) * A_TAP_B);
            #pragma unroll
            for (int kk = 0; kk < 2; ++kk) {
                int kbase = ((qc & 1) << 5) + kk * 16;     // halves within tap
                #pragma unroll
                for (int mt = 0; mt < 4; ++mt) {
                    unsigned int a[4];
                    unsigned int addr = aS + (unsigned)(
                        ((mt * 16 + (lane & 15)) * SAKH
                         + kbase + ((lane >> 4) << 3)) * 2);
                    asm volatile("ldmatrix.sync.aligned.m8n8.x4.shared.b16 "
                                 "{%0,%1,%2,%3}, [%4];"
                                 : "=r"(a[0]), "=r"(a[1]), "=r"(a[2]), "=r"(a[3])
                                 : "r"(addr));
                    #pragma unroll
                    for (int nt = 0; nt < 2; ++nt) {
                        asm volatile(
                            "mma.sync.aligned.m16n8k16.row.col.f32.f16.f16.f32 "
                            "{%0,%1,%2,%3}, {%4,%5,%6,%7}, {%8,%9}, {%0,%1,%2,%3};"
                            : "+f"(acc[mt][nt][0]), "+f"(acc[mt][nt][1]),
                              "+f"(acc[mt][nt][2]), "+f"(acc[mt][nt][3])
                            : "r"(a[0]), "r"(a[1]), "r"(a[2]), "r"(a[3]),
                              "r"(bh[kk][nt][0]), "r"(bh[kk][nt][1]));
                    }
                }
            }
        }

        // Epilogue: out[b][o][l] = acc + bias[o][l]
        #pragma unroll
        for (int mt = 0; mt < 4; ++mt) {
            int r0 = mt * 16 + (lane >> 2);
            #pragma unroll
            for (int nt = 0; nt < 2; ++nt) {
                int c0 = obase + nt * 8 + 2 * (lane & 3);
                float* p = out + (size_t)r0 * (NOC * NL) + (size_t)c0 * NL + l;
                p[0]                         = acc[mt][nt][0] + bz[nt][0];
                p[NL]                        = acc[mt][nt][1] + bz[nt][1];
                p[(size_t)8 * NOC * NL]      = acc[mt][nt][2] + bz[nt][0];
                p[(size_t)8 * NOC * NL + NL] = acc[mt][nt][3] + bz[nt][1];
            }
        }
    }
}

// ---------------------------------------------------------------------------
extern "C" void kernel_launch(void* const* d_in, const int* in_sizes, int n_in,
                              void* d_out, int out_size) {
    const float* x    = (const float*)d_in[0];   // (64,64,32,32)
    const float* wgt  = (const float*)d_in[1];   // (1,576,1024,128)
    const float* bias = (const float*)d_in[2];   // (1,128,32,32)
    float* out = (float*)d_out;                  // (64,128,32,32)

    init_kernel<<<PH * PH, 128>>>();
    transpose_half_kernel<<<dim3(NH, 8), 256>>>(x);
    lc_kernel<<<444, 256>>>(wgt, bias, out);
}

// round 8
// speedup vs baseline: 1.1971x; 1.1971x over previous
#include <cuda_runtime.h>
#include <cuda_fp16.h>

#define NB 64
#define NC 64
#define NH 32
#define NW 32
#define NOC 128
#define NL 1024
#define PH 34
#define NSMS 148

#define SAKH 72                       // A smem row stride (halves)
#define A_TAP_B (64 * SAKH * 2)       // 9216 B
#define WROW 132                      // W smem row stride (floats)
#define W_TAP_B (64 * WROW * 4)       // 33792 B
#define STG_B (A_TAP_B + W_TAP_B)     // 43008 B
#define NSTG 4
#define MBAR_OFF (NSTG * STG_B)       // 172032
#define SMEM_BYTES (MBAR_OFF + 128)

// Scratch: x as fp16, [pixel=(y*34+x)][b][c], border zero.
__device__ __half g_xh[PH * PH * NB * NC];

// ---------------------------------------------------------------------------
__device__ __forceinline__ void cp16(unsigned int s, const void* g) {
    asm volatile("cp.async.cg.shared.global [%0], [%1], 16;" :: "r"(s), "l"(g));
}
__device__ __forceinline__ unsigned int pack_h2(float a, float b) {
    __half2 h = __floats2half2_rn(a, b);
    return *reinterpret_cast<unsigned int*>(&h);
}
__device__ __forceinline__ void mbar_init(unsigned int a, unsigned int c) {
    asm volatile("mbarrier.init.shared.b64 [%0], %1;" :: "r"(a), "r"(c) : "memory");
}
__device__ __forceinline__ void mbar_arrive(unsigned int a) {
    asm volatile("mbarrier.arrive.shared.b64 _, [%0];" :: "r"(a) : "memory");
}
__device__ __forceinline__ void mbar_wait(unsigned int a, int par) {
    asm volatile(
        "{\n\t.reg .pred P;\n\tW%=:\n\t"
        "mbarrier.try_wait.parity.shared.b64 P, [%0], %1;\n\t"
        "@!P bra W%=;\n\t}" :: "r"(a), "r"(par) : "memory");
}

// ---------------------------------------------------------------------------
// Kernel 0: zero border pixels of g_xh. grid 1156 x 128.
// ---------------------------------------------------------------------------
__global__ void __launch_bounds__(128) init_kernel() {
    int p = blockIdx.x;
    int y = p / PH, xx = p % PH;
    if (y == 0 || y == PH - 1 || xx == 0 || xx == PH - 1) {
        uint4* dst = (uint4*)(g_xh + (size_t)p * (NB * NC));
        #pragma unroll
        for (int i = 0; i < 4; ++i)
            dst[threadIdx.x + i * 128] = make_uint4(0, 0, 0, 0);
    }
}

// ---------------------------------------------------------------------------
// Kernel 1: x[b][c][h][w] f32 -> g_xh[(h+1)*34+(w+1)][b][c] fp16.
// ---------------------------------------------------------------------------
__global__ void __launch_bounds__(256) transpose_half_kernel(const float* __restrict__ x) {
    __shared__ __half s[8][64][33];
    int h = blockIdx.x;
    int b0 = blockIdx.y * 8;
    int tid = threadIdx.x;
    for (int idx = tid; idx < 8 * 64 * 32; idx += 256) {
        int b = idx >> 11, c = (idx >> 5) & 63, w = idx & 31;
        float v = x[(((size_t)(b0 + b) * NC + c) * NH + h) * NW + w];
        s[b][c][w] = __float2half_rn(v);
    }
    __syncthreads();
    for (int idx = tid; idx < 32 * 8 * 64; idx += 256) {
        int w = idx >> 9, b = (idx >> 6) & 7, c = idx & 63;
        g_xh[((size_t)((h + 1) * PH + (w + 1)) * NB + (b0 + b)) * NC + c] = s[b][c][w];
    }
}

// ---------------------------------------------------------------------------
// Kernel 2: warp-specialized per-location GEMM.
// 256 thr: warps 0-3 consumers (each 32 OC, full M=64), warps 4-7 producers.
// Stage = one tap (K=64): A fp16 tile + W f32 tile, 4-stage mbarrier ring.
// ---------------------------------------------------------------------------
__global__ void __launch_bounds__(256, 1) lc_kernel(
    const float* __restrict__ w, const float* __restrict__ bias,
    float* __restrict__ out)
{
    extern __shared__ unsigned char smp[];
    unsigned int sbase = (unsigned int)__cvta_generic_to_shared(smp);
    int tid = threadIdx.x, lane = tid & 31, wid = tid >> 5;

    // mbarriers: FULL(s) = base+MBAR_OFF+s*16, EMPTY(s) = +8
    if (tid == 0) {
        #pragma unroll
        for (int s = 0; s < NSTG; ++s) {
            mbar_init(sbase + MBAR_OFF + s * 16, 4);      // full: 4 producer warps
            mbar_init(sbase + MBAR_OFF + s * 16 + 8, 4);  // empty: 4 consumer warps
        }
    }
    __syncthreads();

    int cta = blockIdx.x;
    int nloc = (cta < 136) ? 7 : 6;            // 136*7 + 12*6 = 1024
    int G = nloc * 9;

    if (wid >= 4) {
        // ===================== PRODUCER =====================
        int ptid = tid - 128;
        int loc = 0, tap = 0;
        for (int g = 0; g < G; ++g) {
            int s = g & 3;
            mbar_wait(sbase + MBAR_OFF + s * 16 + 8, ((g >> 2) & 1) ^ 1);
            asm volatile("fence.proxy.async.shared::cta;" ::: "memory");
            int l = cta + NSMS * loc;
            unsigned int aS = sbase + (unsigned)(s * STG_B);
            unsigned int wS = aS + A_TAP_B;
            // A: 64 b-rows x 128B fp16
            const char* xs = (const char*)(g_xh +
                (size_t)(((l >> 5) + tap / 3) * PH + (l & 31) + tap % 3) * (NB * NC));
            #pragma unroll
            for (int f = 0; f < 4; ++f) {
                int idx = ptid + f * 128;
                int r = idx >> 3, j = idx & 7;
                cp16(aS + (unsigned)(r * (SAKH * 2) + j * 16), xs + r * 128 + j * 16);
            }
            // W: 64 ch-rows x 512B f32
            #pragma unroll
            for (int f = 0; f < 16; ++f) {
                int idx = ptid + f * 128;
                int c = idx >> 5, o4 = idx & 31;
                cp16(wS + (unsigned)(c * (WROW * 4) + o4 * 16),
                     w + ((size_t)(c * 9 + tap) * NL + l) * NOC + o4 * 4);
            }
            asm volatile("cp.async.commit_group;" ::: "memory");
            if (g >= 2) {
                asm volatile("cp.async.wait_group 2;" ::: "memory");
                if (lane == 0) mbar_arrive(sbase + MBAR_OFF + ((g - 2) & 3) * 16);
            }
            if (++tap == 9) { tap = 0; ++loc; }
        }
        asm volatile("cp.async.wait_group 1;" ::: "memory");
        if (lane == 0) mbar_arrive(sbase + MBAR_OFF + ((G - 2) & 3) * 16);
        asm volatile("cp.async.wait_group 0;" ::: "memory");
        if (lane == 0) mbar_arrive(sbase + MBAR_OFF + ((G - 1) & 3) * 16);
    } else {
        // ===================== CONSUMER =====================
        int obase = wid * 32;
        float acc[4][4][4];
        float bz[4][2];
        int loc = 0, tap = 0;
        for (int g = 0; g < G; ++g) {
            int s = g & 3;
            int l = cta + NSMS * loc;
            if (tap == 0) {
                #pragma unroll
                for (int nt = 0; nt < 4; ++nt) {
                    int c0 = obase + nt * 8 + 2 * (lane & 3);
                    bz[nt][0] = __ldg(bias + (size_t)c0 * NL + l);
                    bz[nt][1] = __ldg(bias + (size_t)(c0 + 1) * NL + l);
                    #pragma unroll
                    for (int mt = 0; mt < 4; ++mt)
                        #pragma unroll
                        for (int q = 0; q < 4; ++q) acc[mt][nt][q] = 0.f;
                }
            }
            mbar_wait(sbase + MBAR_OFF + s * 16, (g >> 2) & 1);

            unsigned int aS = sbase + (unsigned)(s * STG_B);
            const float* Bs = (const float*)(smp + s * STG_B + A_TAP_B);
            #pragma unroll
            for (int k16 = 0; k16 < 4; ++k16) {
                unsigned int a[4][4], bh[4][2];
                #pragma unroll
                for (int mt = 0; mt < 4; ++mt) {
                    unsigned int addr = aS + (unsigned)(
                        ((mt * 16 + (lane & 15)) * SAKH
                         + k16 * 16 + ((lane >> 4) << 3)) * 2);
                    asm volatile("ldmatrix.sync.aligned.m8n8.x4.shared.b16 "
                                 "{%0,%1,%2,%3}, [%4];"
                                 : "=r"(a[mt][0]), "=r"(a[mt][1]),
                                   "=r"(a[mt][2]), "=r"(a[mt][3])
                                 : "r"(addr));
                }
                int k0 = k16 * 16 + (lane & 3) * 2;
                #pragma unroll
                for (int nt = 0; nt < 4; ++nt) {
                    int col = obase + nt * 8 + (lane >> 2);
                    bh[nt][0] = pack_h2(Bs[k0 * WROW + col], Bs[(k0 + 1) * WROW + col]);
                    bh[nt][1] = pack_h2(Bs[(k0 + 8) * WROW + col], Bs[(k0 + 9) * WROW + col]);
                }
                #pragma unroll
                for (int mt = 0; mt < 4; ++mt)
                    #pragma unroll
                    for (int nt = 0; nt < 4; ++nt) {
                        asm volatile(
                            "mma.sync.aligned.m16n8k16.row.col.f32.f16.f16.f32 "
                            "{%0,%1,%2,%3}, {%4,%5,%6,%7}, {%8,%9}, {%0,%1,%2,%3};"
                            : "+f"(acc[mt][nt][0]), "+f"(acc[mt][nt][1]),
                              "+f"(acc[mt][nt][2]), "+f"(acc[mt][nt][3])
                            : "r"(a[mt][0]), "r"(a[mt][1]), "r"(a[mt][2]), "r"(a[mt][3]),
                              "r"(bh[nt][0]), "r"(bh[nt][1]));
                    }
            }
            if (lane == 0) mbar_arrive(sbase + MBAR_OFF + s * 16 + 8);

            if (tap == 8) {
                #pragma unroll
                for (int mt = 0; mt < 4; ++mt) {
                    int r0 = mt * 16 + (lane >> 2);
                    #pragma unroll
                    for (int nt = 0; nt < 4; ++nt) {
                        int c0 = obase + nt * 8 + 2 * (lane & 3);
                        float* p = out + (size_t)r0 * (NOC * NL) + (size_t)c0 * NL + l;
                        p[0]                         = acc[mt][nt][0] + bz[nt][0];
                        p[NL]                        = acc[mt][nt][1] + bz[nt][1];
                        p[(size_t)8 * NOC * NL]      = acc[mt][nt][2] + bz[nt][0];
                        p[(size_t)8 * NOC * NL + NL] = acc[mt][nt][3] + bz[nt][1];
                    }
                }
            }
            if (++tap == 9) { tap = 0; ++loc; }
        }
    }
}

// ---------------------------------------------------------------------------
extern "C" void kernel_launch(void* const* d_in, const int* in_sizes, int n_in,
                              void* d_out, int out_size) {
    const float* x    = (const float*)d_in[0];   // (64,64,32,32)
    const float* wgt  = (const float*)d_in[1];   // (1,576,1024,128)
    const float* bias = (const float*)d_in[2];   // (1,128,32,32)
    float* out = (float*)d_out;                  // (64,128,32,32)

    cudaFuncSetAttribute(lc_kernel,
                         cudaFuncAttributeMaxDynamicSharedMemorySize, SMEM_BYTES);

    init_kernel<<<PH * PH, 128>>>();
    transpose_half_kernel<<<dim3(NH, 8), 256>>>(x);
    lc_kernel<<<NSMS, 256, SMEM_BYTES>>>(wgt, bias, out);
}